// round 1
// baseline (speedup 1.0000x reference)
#include <cuda_runtime.h>
#include <cuda_bf16.h>
#include <math.h>

// Problem constants
#define IDIM 512
#define HDIM 512
#define BDIM 8
#define SDIM 4096
#define MROWS (BDIM * SDIM)   // 32768 tokens, all independent

// GEMM tiling
#define TM 128
#define TN 128
#define TK 8
#define NTHREADS 256

// Scratch activation buffers (64 MB each) — static device arrays, no allocs.
__device__ float g_bufA[(size_t)MROWS * HDIM];
__device__ float g_bufB[(size_t)MROWS * HDIM];
__device__ float g_bufC[(size_t)MROWS * HDIM];

// out[m][n] = sum_k A[m][k] * W[n][k]  (+ optional second pair)  + biases, opt tanh.
// A: [MROWS, 512] row-major, W: [512, 512] row-major (K contiguous) -> NT GEMM,
// both operands coalesce on K.
template<bool DUAL, bool DO_TANH, bool TRANS_OUT, bool HSFIN>
__global__ __launch_bounds__(NTHREADS, 2)
void rnn_gemm(const float* __restrict__ A0, const float* __restrict__ W0,
              const float* __restrict__ A1, const float* __restrict__ W1,
              const float* __restrict__ bias0, const float* __restrict__ bias1,
              float* __restrict__ C, float* __restrict__ hsf)
{
    __shared__ float As[TK][TM];   // [k][m]
    __shared__ float Bs[TK][TN];   // [k][n]

    const int t    = threadIdx.x;
    const int lrow = t >> 1;              // 0..127
    const int lseg = (t & 1) << 2;        // 0 or 4
    const int tx   = t & 15;              // 0..15 -> n
    const int ty   = t >> 4;              // 0..15 -> m
    const int m0   = blockIdx.y * TM;
    const int n0   = blockIdx.x * TN;

    float acc[8][8];
#pragma unroll
    for (int i = 0; i < 8; ++i)
#pragma unroll
        for (int j = 0; j < 8; ++j) acc[i][j] = 0.0f;

    const int NPASS = DUAL ? 2 : 1;
#pragma unroll 1
    for (int pass = 0; pass < NPASS; ++pass) {
        const float* __restrict__ A = (DUAL && pass) ? A1 : A0;
        const float* __restrict__ W = (DUAL && pass) ? W1 : W0;
        const float* arow = A + (size_t)(m0 + lrow) * 512 + lseg;
        const float* wrow = W + (size_t)(n0 + lrow) * 512 + lseg;

        // preload k-tile 0 (previous pass ended right after a __syncthreads,
        // so smem is free to overwrite)
        {
            float4 av = *(const float4*)(arow);
            float4 wv = *(const float4*)(wrow);
            As[lseg + 0][lrow] = av.x; As[lseg + 1][lrow] = av.y;
            As[lseg + 2][lrow] = av.z; As[lseg + 3][lrow] = av.w;
            Bs[lseg + 0][lrow] = wv.x; Bs[lseg + 1][lrow] = wv.y;
            Bs[lseg + 2][lrow] = wv.z; Bs[lseg + 3][lrow] = wv.w;
        }
        __syncthreads();

#pragma unroll 1
        for (int kt = 0; kt < 512 / TK; ++kt) {
            // register-staged prefetch of next k-tile (latency hidden by FMAs)
            float4 av, wv;
            if (kt < 63) {
                av = *(const float4*)(arow + (kt + 1) * TK);
                wv = *(const float4*)(wrow + (kt + 1) * TK);
            }

#pragma unroll
            for (int kk = 0; kk < TK; ++kk) {
                float4 a0 = *(const float4*)(&As[kk][ty * 8]);
                float4 a1 = *(const float4*)(&As[kk][ty * 8 + 4]);
                float4 w0 = *(const float4*)(&Bs[kk][tx * 8]);
                float4 w1 = *(const float4*)(&Bs[kk][tx * 8 + 4]);
                float af[8] = {a0.x, a0.y, a0.z, a0.w, a1.x, a1.y, a1.z, a1.w};
                float wf[8] = {w0.x, w0.y, w0.z, w0.w, w1.x, w1.y, w1.z, w1.w};
#pragma unroll
                for (int i = 0; i < 8; ++i)
#pragma unroll
                    for (int j = 0; j < 8; ++j)
                        acc[i][j] = fmaf(af[i], wf[j], acc[i][j]);
            }
            __syncthreads();
            if (kt < 63) {
                As[lseg + 0][lrow] = av.x; As[lseg + 1][lrow] = av.y;
                As[lseg + 2][lrow] = av.z; As[lseg + 3][lrow] = av.w;
                Bs[lseg + 0][lrow] = wv.x; Bs[lseg + 1][lrow] = wv.y;
                Bs[lseg + 2][lrow] = wv.z; Bs[lseg + 3][lrow] = wv.w;
                __syncthreads();
            }
        }
    }

    // ---- epilogue ----
    float bv[8];
#pragma unroll
    for (int j = 0; j < 8; ++j) {
        int n = n0 + tx * 8 + j;
        float b = bias0[n];
        if (bias1) b += bias1[n];
        bv[j] = b;
    }

#pragma unroll
    for (int i = 0; i < 8; ++i) {
        int m = m0 + ty * 8 + i;
        float v[8];
#pragma unroll
        for (int j = 0; j < 8; ++j) {
            float x = acc[i][j] + bv[j];
            if (DO_TANH) x = tanhf(x);
            v[j] = x;
        }
        float4 v0 = make_float4(v[0], v[1], v[2], v[3]);
        float4 v1 = make_float4(v[4], v[5], v[6], v[7]);

        float* dst;
        if (TRANS_OUT) {
            int s = m & (SDIM - 1);
            int b = m >> 12;  // m / SDIM
            dst = C + ((size_t)s * BDIM + b) * HDIM + n0 + tx * 8;
        } else {
            dst = C + (size_t)m * HDIM + n0 + tx * 8;
        }
        *(float4*)(dst)     = v0;
        *(float4*)(dst + 4) = v1;

        if (HSFIN) {
            if ((m & (SDIM - 1)) == SDIM - 1) {
                float* h = hsf + (size_t)(m >> 12) * HDIM + n0 + tx * 8;
                *(float4*)(h)     = v0;
                *(float4*)(h + 4) = v1;
            }
        }
    }
}

extern "C" void kernel_launch(void* const* d_in, const int* in_sizes, int n_in,
                              void* d_out, int out_size)
{
    // metadata order:
    // 0 xs, 1 W_xh0, 2 b_xh0, 3 W_hh0(unused), 4 b_hh0, 5 W_hy0, 6 b_hy0,
    // 7 W_xh_h, 8 b_xh_h, 9 W_hh_h, 10 b_hh_h, 11 W_hy_h, 12 b_hy_h
    const float* xs     = (const float*)d_in[0];
    const float* W_xh0  = (const float*)d_in[1];
    const float* b_xh0  = (const float*)d_in[2];
    const float* b_hh0  = (const float*)d_in[4];
    const float* W_hy0  = (const float*)d_in[5];
    const float* b_hy0  = (const float*)d_in[6];
    const float* W_xh_h = (const float*)d_in[7];
    const float* b_xh_h = (const float*)d_in[8];
    const float* W_hh_h = (const float*)d_in[9];
    const float* b_hh_h = (const float*)d_in[10];
    const float* W_hy_h = (const float*)d_in[11];
    const float* b_hy_h = (const float*)d_in[12];

    float* out = (float*)d_out;
    float* hs_final = out + (size_t)SDIM * BDIM * HDIM;

    float *bufA, *bufB, *bufC;
    cudaGetSymbolAddress((void**)&bufA, g_bufA);
    cudaGetSymbolAddress((void**)&bufB, g_bufB);
    cudaGetSymbolAddress((void**)&bufC, g_bufC);

    dim3 grid(HDIM / TN, MROWS / TM);   // (4, 256)
    dim3 block(NTHREADS);

    const size_t WSTRIDE = (size_t)HDIM * HDIM;

    // 1) h0 = tanh(X @ W_xh0^T + b_xh0 + b_hh0)           -> bufA
    rnn_gemm<false, true,  false, false><<<grid, block>>>(
        xs, W_xh0, nullptr, nullptr, b_xh0, b_hh0, bufA, nullptr);
    // 2) y0 = h0 @ W_hy0^T + b_hy0                        -> bufB
    rnn_gemm<false, false, false, false><<<grid, block>>>(
        bufA, W_hy0, nullptr, nullptr, b_hy0, nullptr, bufB, nullptr);
    // 3) h1 = tanh(h0@W_hh_h[0]^T + y0@W_xh_h[0]^T + b)   -> bufC
    rnn_gemm<true,  true,  false, false><<<grid, block>>>(
        bufA, W_hh_h, bufB, W_xh_h, b_hh_h, b_xh_h, bufC, nullptr);
    // 4) y1 = h1 @ W_hy_h[0]^T + b_hy_h[0]                -> bufB
    rnn_gemm<false, false, false, false><<<grid, block>>>(
        bufC, W_hy_h, nullptr, nullptr, b_hy_h, nullptr, bufB, nullptr);
    // 5) h2 = tanh(h1@W_hh_h[1]^T + y1@W_xh_h[1]^T + b)   -> bufA (+ hs_final)
    rnn_gemm<true,  true,  false, true ><<<grid, block>>>(
        bufC, W_hh_h + WSTRIDE, bufB, W_xh_h + WSTRIDE,
        b_hh_h + HDIM, b_xh_h + HDIM, bufA, hs_final);
    // 6) outputs = (h2 @ W_hy_h[1]^T + b_hy_h[1]) transposed to [S,B,H] -> out
    rnn_gemm<false, false, true,  false><<<grid, block>>>(
        bufA, W_hy_h + WSTRIDE, nullptr, nullptr,
        b_hy_h + HDIM, nullptr, out, nullptr);
}

// round 2
// speedup vs baseline: 1.0007x; 1.0007x over previous
#include <cuda_runtime.h>
#include <cuda_bf16.h>
#include <math.h>

// Problem constants
#define IDIM 512
#define HDIM 512
#define BDIM 8
#define SDIM 4096
#define MROWS (BDIM * SDIM)   // 32768 tokens, all independent

// GEMM tiling
#define TM 128
#define TN 128
#define TK 8
#define NTHREADS 256

// Scratch activation buffers (64 MB each) — static device arrays, no allocs.
__device__ float g_bufA[(size_t)MROWS * HDIM];
__device__ float g_bufB[(size_t)MROWS * HDIM];
__device__ float g_bufC[(size_t)MROWS * HDIM];

// out[m][n] = sum_k A[m][k] * W[n][k]  (+ optional second pair)  + biases, opt tanh.
// A: [MROWS, 512] row-major, W: [512, 512] row-major (K contiguous) -> NT GEMM,
// both operands coalesce on K.
template<bool DUAL, bool DO_TANH, bool TRANS_OUT, bool HSFIN>
__global__ __launch_bounds__(NTHREADS, 2)
void rnn_gemm(const float* __restrict__ A0, const float* __restrict__ W0,
              const float* __restrict__ A1, const float* __restrict__ W1,
              const float* __restrict__ bias0, const float* __restrict__ bias1,
              float* __restrict__ C, float* __restrict__ hsf)
{
    __shared__ float As[TK][TM];   // [k][m]
    __shared__ float Bs[TK][TN];   // [k][n]

    const int t    = threadIdx.x;
    const int lrow = t >> 1;              // 0..127
    const int lseg = (t & 1) << 2;        // 0 or 4
    const int tx   = t & 15;              // 0..15 -> n
    const int ty   = t >> 4;              // 0..15 -> m
    const int m0   = blockIdx.y * TM;
    const int n0   = blockIdx.x * TN;

    float acc[8][8];
#pragma unroll
    for (int i = 0; i < 8; ++i)
#pragma unroll
        for (int j = 0; j < 8; ++j) acc[i][j] = 0.0f;

    const int NPASS = DUAL ? 2 : 1;
#pragma unroll 1
    for (int pass = 0; pass < NPASS; ++pass) {
        const float* __restrict__ A = (DUAL && pass) ? A1 : A0;
        const float* __restrict__ W = (DUAL && pass) ? W1 : W0;
        const float* arow = A + (size_t)(m0 + lrow) * 512 + lseg;
        const float* wrow = W + (size_t)(n0 + lrow) * 512 + lseg;

        // preload k-tile 0 (previous pass ended right after a __syncthreads,
        // so smem is free to overwrite)
        {
            float4 av = *(const float4*)(arow);
            float4 wv = *(const float4*)(wrow);
            As[lseg + 0][lrow] = av.x; As[lseg + 1][lrow] = av.y;
            As[lseg + 2][lrow] = av.z; As[lseg + 3][lrow] = av.w;
            Bs[lseg + 0][lrow] = wv.x; Bs[lseg + 1][lrow] = wv.y;
            Bs[lseg + 2][lrow] = wv.z; Bs[lseg + 3][lrow] = wv.w;
        }
        __syncthreads();

#pragma unroll 1
        for (int kt = 0; kt < 512 / TK; ++kt) {
            // register-staged prefetch of next k-tile (latency hidden by FMAs)
            float4 av, wv;
            if (kt < 63) {
                av = *(const float4*)(arow + (kt + 1) * TK);
                wv = *(const float4*)(wrow + (kt + 1) * TK);
            }

#pragma unroll
            for (int kk = 0; kk < TK; ++kk) {
                float4 a0 = *(const float4*)(&As[kk][ty * 8]);
                float4 a1 = *(const float4*)(&As[kk][ty * 8 + 4]);
                float4 w0 = *(const float4*)(&Bs[kk][tx * 8]);
                float4 w1 = *(const float4*)(&Bs[kk][tx * 8 + 4]);
                float af[8] = {a0.x, a0.y, a0.z, a0.w, a1.x, a1.y, a1.z, a1.w};
                float wf[8] = {w0.x, w0.y, w0.z, w0.w, w1.x, w1.y, w1.z, w1.w};
#pragma unroll
                for (int i = 0; i < 8; ++i)
#pragma unroll
                    for (int j = 0; j < 8; ++j)
                        acc[i][j] = fmaf(af[i], wf[j], acc[i][j]);
            }
            __syncthreads();
            if (kt < 63) {
                As[lseg + 0][lrow] = av.x; As[lseg + 1][lrow] = av.y;
                As[lseg + 2][lrow] = av.z; As[lseg + 3][lrow] = av.w;
                Bs[lseg + 0][lrow] = wv.x; Bs[lseg + 1][lrow] = wv.y;
                Bs[lseg + 2][lrow] = wv.z; Bs[lseg + 3][lrow] = wv.w;
                __syncthreads();
            }
        }
    }

    // ---- epilogue ----
    float bv[8];
#pragma unroll
    for (int j = 0; j < 8; ++j) {
        int n = n0 + tx * 8 + j;
        float b = bias0[n];
        if (bias1) b += bias1[n];
        bv[j] = b;
    }

#pragma unroll
    for (int i = 0; i < 8; ++i) {
        int m = m0 + ty * 8 + i;
        float v[8];
#pragma unroll
        for (int j = 0; j < 8; ++j) {
            float x = acc[i][j] + bv[j];
            if (DO_TANH) x = tanhf(x);
            v[j] = x;
        }
        float4 v0 = make_float4(v[0], v[1], v[2], v[3]);
        float4 v1 = make_float4(v[4], v[5], v[6], v[7]);

        float* dst;
        if (TRANS_OUT) {
            int s = m & (SDIM - 1);
            int b = m >> 12;  // m / SDIM
            dst = C + ((size_t)s * BDIM + b) * HDIM + n0 + tx * 8;
        } else {
            dst = C + (size_t)m * HDIM + n0 + tx * 8;
        }
        *(float4*)(dst)     = v0;
        *(float4*)(dst + 4) = v1;

        if (HSFIN) {
            if ((m & (SDIM - 1)) == SDIM - 1) {
                float* h = hsf + (size_t)(m >> 12) * HDIM + n0 + tx * 8;
                *(float4*)(h)     = v0;
                *(float4*)(h + 4) = v1;
            }
        }
    }
}

extern "C" void kernel_launch(void* const* d_in, const int* in_sizes, int n_in,
                              void* d_out, int out_size)
{
    // metadata order:
    // 0 xs, 1 W_xh0, 2 b_xh0, 3 W_hh0(unused), 4 b_hh0, 5 W_hy0, 6 b_hy0,
    // 7 W_xh_h, 8 b_xh_h, 9 W_hh_h, 10 b_hh_h, 11 W_hy_h, 12 b_hy_h
    const float* xs     = (const float*)d_in[0];
    const float* W_xh0  = (const float*)d_in[1];
    const float* b_xh0  = (const float*)d_in[2];
    const float* b_hh0  = (const float*)d_in[4];
    const float* W_hy0  = (const float*)d_in[5];
    const float* b_hy0  = (const float*)d_in[6];
    const float* W_xh_h = (const float*)d_in[7];
    const float* b_xh_h = (const float*)d_in[8];
    const float* W_hh_h = (const float*)d_in[9];
    const float* b_hh_h = (const float*)d_in[10];
    const float* W_hy_h = (const float*)d_in[11];
    const float* b_hy_h = (const float*)d_in[12];

    float* out = (float*)d_out;
    float* hs_final = out + (size_t)SDIM * BDIM * HDIM;

    float *bufA, *bufB, *bufC;
    cudaGetSymbolAddress((void**)&bufA, g_bufA);
    cudaGetSymbolAddress((void**)&bufB, g_bufB);
    cudaGetSymbolAddress((void**)&bufC, g_bufC);

    dim3 grid(HDIM / TN, MROWS / TM);   // (4, 256)
    dim3 block(NTHREADS);

    const size_t WSTRIDE = (size_t)HDIM * HDIM;

    // 1) h0 = tanh(X @ W_xh0^T + b_xh0 + b_hh0)           -> bufA
    rnn_gemm<false, true,  false, false><<<grid, block>>>(
        xs, W_xh0, nullptr, nullptr, b_xh0, b_hh0, bufA, nullptr);
    // 2) y0 = h0 @ W_hy0^T + b_hy0                        -> bufB
    rnn_gemm<false, false, false, false><<<grid, block>>>(
        bufA, W_hy0, nullptr, nullptr, b_hy0, nullptr, bufB, nullptr);
    // 3) h1 = tanh(h0@W_hh_h[0]^T + y0@W_xh_h[0]^T + b)   -> bufC
    rnn_gemm<true,  true,  false, false><<<grid, block>>>(
        bufA, W_hh_h, bufB, W_xh_h, b_hh_h, b_xh_h, bufC, nullptr);
    // 4) y1 = h1 @ W_hy_h[0]^T + b_hy_h[0]                -> bufB
    rnn_gemm<false, false, false, false><<<grid, block>>>(
        bufC, W_hy_h, nullptr, nullptr, b_hy_h, nullptr, bufB, nullptr);
    // 5) h2 = tanh(h1@W_hh_h[1]^T + y1@W_xh_h[1]^T + b)   -> bufA (+ hs_final)
    rnn_gemm<true,  true,  false, true ><<<grid, block>>>(
        bufC, W_hh_h + WSTRIDE, bufB, W_xh_h + WSTRIDE,
        b_hh_h + HDIM, b_xh_h + HDIM, bufA, hs_final);
    // 6) outputs = (h2 @ W_hy_h[1]^T + b_hy_h[1]) transposed to [S,B,H] -> out
    rnn_gemm<false, false, true,  false><<<grid, block>>>(
        bufA, W_hy_h + WSTRIDE, nullptr, nullptr,
        b_hy_h + HDIM, nullptr, out, nullptr);
}

// round 4
// speedup vs baseline: 2.7064x; 2.7046x over previous
#include <cuda_runtime.h>
#include <cuda_bf16.h>
#include <math.h>
#include <cstdint>
#include <cstddef>

typedef __nv_bfloat16 bf16;

#define MROWS 32768
#define HD    512
#define WSZ   (512*512)

#define BM 128
#define BN 256
#define KC 64
#define NTH 256

// stage layout (bytes from stage base): Ah 0, Al 16K, Wh 32K, Wl 64K
#define AH_OFF 0u
#define AL_OFF 16384u
#define WH_OFF 32768u
#define WL_OFF 65536u
#define STAGE  98304u
#define SMEMB  (1024u + 2u*STAGE)   // 197632

// ------------- scratch (static device arrays, no runtime alloc) -------------
__device__ bf16 g_Xh[(size_t)MROWS*HD];
__device__ bf16 g_Xl[(size_t)MROWS*HD];
__device__ bf16 g_H0h[(size_t)MROWS*HD];
__device__ bf16 g_H0l[(size_t)MROWS*HD];
__device__ bf16 g_H1h[(size_t)MROWS*HD];
__device__ bf16 g_H1l[(size_t)MROWS*HD];
__device__ bf16 g_Yh[(size_t)MROWS*HD];
__device__ bf16 g_Yl[(size_t)MROWS*HD];
__device__ bf16 g_Wh[8*WSZ];
__device__ bf16 g_Wl[8*WSZ];

// ----------------------------- PTX helpers ----------------------------------
__device__ __forceinline__ uint32_t s2u(const void* p) {
    uint32_t a;
    asm("{ .reg .u64 t; cvta.to.shared.u64 t, %1; cvt.u32.u64 %0, t; }" : "=r"(a) : "l"(p));
    return a;
}
__device__ __forceinline__ void cp16(uint32_t dst, const void* src) {
    asm volatile("cp.async.cg.shared.global [%0], [%1], 16;" :: "r"(dst), "l"(src));
}
#define CP_COMMIT() asm volatile("cp.async.commit_group;" ::: "memory")

__device__ __forceinline__ void ldsm4(uint32_t& r0, uint32_t& r1, uint32_t& r2,
                                      uint32_t& r3, uint32_t addr) {
    asm volatile("ldmatrix.sync.aligned.m8n8.x4.shared.b16 {%0,%1,%2,%3}, [%4];"
                 : "=r"(r0), "=r"(r1), "=r"(r2), "=r"(r3) : "r"(addr));
}
__device__ __forceinline__ void mma16816(float* c, const uint32_t* a, const uint32_t* b) {
    asm volatile(
        "mma.sync.aligned.m16n8k16.row.col.f32.bf16.bf16.f32 "
        "{%0,%1,%2,%3}, {%4,%5,%6,%7}, {%8,%9}, {%0,%1,%2,%3};"
        : "+f"(c[0]), "+f"(c[1]), "+f"(c[2]), "+f"(c[3])
        : "r"(a[0]), "r"(a[1]), "r"(a[2]), "r"(a[3]), "r"(b[0]), "r"(b[1]));
}

// fast accurate tanh: 1 - 2/(exp(2x)+1); ex2/rcp approx err ~2^-22
__device__ __forceinline__ float tfast(float x) {
    float e, r;
    asm("ex2.approx.f32 %0, %1;" : "=f"(e) : "f"(x * 2.8853900817779268f));
    asm("rcp.approx.f32 %0, %1;" : "=f"(r) : "f"(e + 1.0f));
    return fmaf(-2.0f, r, 1.0f);
}

// ---------------------------- GEMM stage kernel -----------------------------
// acc[m][n] = sum_k A0[m][k]*W0[n][k] (+A1*W1 if DUAL) + bias, opt tanh.
// A/W given as bf16 (hi,lo) pairs; computes Ah*Wh + Ah*Wl + Al*Wh (fp32 acc).
template<bool DUAL, bool DO_TANH, bool HSF, bool TRANS>
__global__ void __launch_bounds__(NTH, 1) gemm_stage(
    const bf16* __restrict__ Ah0, const bf16* __restrict__ Al0,
    const bf16* __restrict__ Wh0, const bf16* __restrict__ Wl0,
    const bf16* __restrict__ Ah1, const bf16* __restrict__ Al1,
    const bf16* __restrict__ Wh1, const bf16* __restrict__ Wl1,
    const float* __restrict__ bias0, const float* __restrict__ bias1,
    bf16* __restrict__ outH, bf16* __restrict__ outL,
    float* __restrict__ outF, float* __restrict__ hsf)
{
    extern __shared__ char smem[];
    const uint32_t sb = s2u(smem);
    const int t   = threadIdx.x;
    const int wid = t >> 5;
    const int lid = t & 31;
    const int n0  = blockIdx.x * BN;
    const int m0  = blockIdx.y * BM;
    const int wm  = wid >> 2;      // 0..1  (M)
    const int wn  = wid & 3;       // 0..3  (N)

    if (t < BN) {
        float b = bias0[n0 + t];
        if (bias1) b += bias1[n0 + t];
        ((float*)smem)[t] = b;
    }

    float acc[4][8][4];
#pragma unroll
    for (int mt = 0; mt < 4; ++mt)
#pragma unroll
        for (int nt = 0; nt < 8; ++nt)
#pragma unroll
            for (int e = 0; e < 4; ++e) acc[mt][nt][e] = 0.0f;

    // ldmatrix per-lane addressing
    const int q   = lid >> 3;        // matrix quadrant 0..3
    const int lr8 = lid & 7;
    const int sws = lr8;             // swizzle key = row & 7
    const uint32_t aOff = (uint32_t)((wm * 64 + (q & 1) * 8 + lr8) * 128);
    const int aHalf = q >> 1;
    const uint32_t bOff = (uint32_t)((wn * 64 + (q >> 1) * 8 + lr8) * 128);
    const int bHalf = q & 1;

    const int NC = DUAL ? 16 : 8;

    auto load_chunk = [&](int cc) {
        const bf16* Ah = (DUAL && cc >= 8) ? Ah1 : Ah0;
        const bf16* Al = (DUAL && cc >= 8) ? Al1 : Al0;
        const bf16* Wh = (DUAL && cc >= 8) ? Wh1 : Wh0;
        const bf16* Wl = (DUAL && cc >= 8) ? Wl1 : Wl0;
        const int k0 = (cc & 7) * KC;
        const uint32_t st = sb + 1024 + (cc & 1) * STAGE;
#pragma unroll
        for (int i = 0; i < 4; ++i) {                 // A: 128 rows x 8 cols16
            int idx = t + i * NTH;
            int r = idx >> 3, c = idx & 7;
            uint32_t d = st + r * 128 + (uint32_t)((c ^ (r & 7)) << 4);
            size_t so = (size_t)(m0 + r) * HD + k0 + c * 8;
            cp16(d + AH_OFF, Ah + so);
            cp16(d + AL_OFF, Al + so);
        }
#pragma unroll
        for (int i = 0; i < 8; ++i) {                 // W: 256 rows x 8 cols16
            int idx = t + i * NTH;
            int r = idx >> 3, c = idx & 7;
            uint32_t d = st + r * 128 + (uint32_t)((c ^ (r & 7)) << 4);
            size_t so = (size_t)(n0 + r) * HD + k0 + c * 8;
            cp16(d + WH_OFF, Wh + so);
            cp16(d + WL_OFF, Wl + so);
        }
        CP_COMMIT();
    };

    load_chunk(0);
    load_chunk(1);

#pragma unroll 1
    for (int cc = 0; cc < NC; ++cc) {
        if (cc < NC - 1) asm volatile("cp.async.wait_group 1;" ::: "memory");
        else             asm volatile("cp.async.wait_group 0;" ::: "memory");
        __syncthreads();

        const uint32_t st = sb + 1024 + (cc & 1) * STAGE;
        const uint32_t aB = st + aOff;
        const uint32_t bB = st + bOff;

#pragma unroll
        for (int ks = 0; ks < 4; ++ks) {
            const uint32_t ca = (uint32_t)(((2 * ks + aHalf) ^ sws) << 4);
            const uint32_t cb = (uint32_t)(((2 * ks + bHalf) ^ sws) << 4);
            uint32_t a[4][4], b[8][2];

            // A_hi fragments
#pragma unroll
            for (int mt = 0; mt < 4; ++mt)
                ldsm4(a[mt][0], a[mt][1], a[mt][2], a[mt][3],
                      aB + AH_OFF + mt * 2048 + ca);
            // W_lo fragments -> acc += Ah*Wl
#pragma unroll
            for (int bt = 0; bt < 4; ++bt)
                ldsm4(b[2*bt][0], b[2*bt][1], b[2*bt+1][0], b[2*bt+1][1],
                      bB + WL_OFF + bt * 2048 + cb);
#pragma unroll
            for (int mt = 0; mt < 4; ++mt)
#pragma unroll
                for (int nt = 0; nt < 8; ++nt)
                    mma16816(acc[mt][nt], a[mt], b[nt]);
            // W_hi fragments -> acc += Ah*Wh
#pragma unroll
            for (int bt = 0; bt < 4; ++bt)
                ldsm4(b[2*bt][0], b[2*bt][1], b[2*bt+1][0], b[2*bt+1][1],
                      bB + WH_OFF + bt * 2048 + cb);
#pragma unroll
            for (int mt = 0; mt < 4; ++mt)
#pragma unroll
                for (int nt = 0; nt < 8; ++nt)
                    mma16816(acc[mt][nt], a[mt], b[nt]);
            // A_lo fragments -> acc += Al*Wh
#pragma unroll
            for (int mt = 0; mt < 4; ++mt)
                ldsm4(a[mt][0], a[mt][1], a[mt][2], a[mt][3],
                      aB + AL_OFF + mt * 2048 + ca);
#pragma unroll
            for (int mt = 0; mt < 4; ++mt)
#pragma unroll
                for (int nt = 0; nt < 8; ++nt)
                    mma16816(acc[mt][nt], a[mt], b[nt]);
        }

        __syncthreads();
        if (cc + 2 < NC) load_chunk(cc + 2);
    }

    // ------------------------------ epilogue --------------------------------
    const float* bsm = (const float*)smem;
    const int lq = lid >> 2;      // row within 8
    const int lr = lid & 3;       // col pair

#pragma unroll
    for (int mt = 0; mt < 4; ++mt) {
#pragma unroll
        for (int hf = 0; hf < 2; ++hf) {
            const int m = m0 + wm * 64 + mt * 16 + lq + hf * 8;
            const int nbase = n0 + wn * 64;
#pragma unroll
            for (int nt = 0; nt < 8; ++nt) {
                const int nn = nt * 8 + lr * 2;
                float x0 = acc[mt][nt][hf * 2 + 0] + bsm[wn * 64 + nn];
                float x1 = acc[mt][nt][hf * 2 + 1] + bsm[wn * 64 + nn + 1];
                if (DO_TANH) { x0 = tfast(x0); x1 = tfast(x1); }

                if (TRANS) {
                    const int s = m & 4095, bb = m >> 12;
                    float* dst = outF + ((size_t)(s * 8 + bb)) * HD + nbase + nn;
                    *(float2*)dst = make_float2(x0, x1);
                } else {
                    __nv_bfloat162 hh, ll;
                    hh.x = __float2bfloat16_rn(x0);
                    hh.y = __float2bfloat16_rn(x1);
                    ll.x = __float2bfloat16_rn(x0 - __bfloat162float(hh.x));
                    ll.y = __float2bfloat16_rn(x1 - __bfloat162float(hh.y));
                    *(__nv_bfloat162*)(outH + (size_t)m * HD + nbase + nn) = hh;
                    *(__nv_bfloat162*)(outL + (size_t)m * HD + nbase + nn) = ll;
                }
                if (HSF && ((m & 4095) == 4095)) {
                    float* hd = hsf + (size_t)(m >> 12) * HD + nbase + nn;
                    *(float2*)hd = make_float2(x0, x1);
                }
            }
        }
    }
}

// ------------------------------- prep kernels -------------------------------
__global__ void k_split_x(const float* __restrict__ x,
                          bf16* __restrict__ xh, bf16* __restrict__ xl)
{
    size_t i = ((size_t)blockIdx.x * blockDim.x + threadIdx.x) * 4;
    float4 v = *(const float4*)(x + i);
    float vv[4] = {v.x, v.y, v.z, v.w};
    __nv_bfloat162 h0, h1, l0, l1;
    h0.x = __float2bfloat16_rn(vv[0]); h0.y = __float2bfloat16_rn(vv[1]);
    h1.x = __float2bfloat16_rn(vv[2]); h1.y = __float2bfloat16_rn(vv[3]);
    l0.x = __float2bfloat16_rn(vv[0] - __bfloat162float(h0.x));
    l0.y = __float2bfloat16_rn(vv[1] - __bfloat162float(h0.y));
    l1.x = __float2bfloat16_rn(vv[2] - __bfloat162float(h1.x));
    l1.y = __float2bfloat16_rn(vv[3] - __bfloat162float(h1.y));
    ((__nv_bfloat162*)(xh + i))[0] = h0;
    ((__nv_bfloat162*)(xh + i))[1] = h1;
    ((__nv_bfloat162*)(xl + i))[0] = l0;
    ((__nv_bfloat162*)(xl + i))[1] = l1;
}

struct WPtrs { const float* p[8]; };

__global__ void k_split_w(WPtrs wp, bf16* __restrict__ wh, bf16* __restrict__ wl)
{
    size_t e = ((size_t)blockIdx.x * blockDim.x + threadIdx.x) * 4;
    int slot = (int)(e >> 18);
    size_t off = e & (WSZ - 1);
    float4 v = *(const float4*)(wp.p[slot] + off);
    float vv[4] = {v.x, v.y, v.z, v.w};
    __nv_bfloat162 h0, h1, l0, l1;
    h0.x = __float2bfloat16_rn(vv[0]); h0.y = __float2bfloat16_rn(vv[1]);
    h1.x = __float2bfloat16_rn(vv[2]); h1.y = __float2bfloat16_rn(vv[3]);
    l0.x = __float2bfloat16_rn(vv[0] - __bfloat162float(h0.x));
    l0.y = __float2bfloat16_rn(vv[1] - __bfloat162float(h0.y));
    l1.x = __float2bfloat16_rn(vv[2] - __bfloat162float(h1.x));
    l1.y = __float2bfloat16_rn(vv[3] - __bfloat162float(h1.y));
    ((__nv_bfloat162*)(wh + e))[0] = h0;
    ((__nv_bfloat162*)(wh + e))[1] = h1;
    ((__nv_bfloat162*)(wl + e))[0] = l0;
    ((__nv_bfloat162*)(wl + e))[1] = l1;
}

// --------------------------------- launcher ---------------------------------
extern "C" void kernel_launch(void* const* d_in, const int* in_sizes, int n_in,
                              void* d_out, int out_size)
{
    const float* xs     = (const float*)d_in[0];
    const float* W_xh0  = (const float*)d_in[1];
    const float* b_xh0  = (const float*)d_in[2];
    const float* b_hh0  = (const float*)d_in[4];
    const float* W_hy0  = (const float*)d_in[5];
    const float* b_hy0  = (const float*)d_in[6];
    const float* W_xh_h = (const float*)d_in[7];
    const float* b_xh_h = (const float*)d_in[8];
    const float* W_hh_h = (const float*)d_in[9];
    const float* b_hh_h = (const float*)d_in[10];
    const float* W_hy_h = (const float*)d_in[11];
    const float* b_hy_h = (const float*)d_in[12];

    float* out = (float*)d_out;
    float* hs_final = out + (size_t)4096 * 8 * HD;

    bf16 *Xh, *Xl, *H0h, *H0l, *H1h, *H1l, *Yh, *Yl, *Wh, *Wl;
    cudaGetSymbolAddress((void**)&Xh,  g_Xh);
    cudaGetSymbolAddress((void**)&Xl,  g_Xl);
    cudaGetSymbolAddress((void**)&H0h, g_H0h);
    cudaGetSymbolAddress((void**)&H0l, g_H0l);
    cudaGetSymbolAddress((void**)&H1h, g_H1h);
    cudaGetSymbolAddress((void**)&H1l, g_H1l);
    cudaGetSymbolAddress((void**)&Yh,  g_Yh);
    cudaGetSymbolAddress((void**)&Yl,  g_Yl);
    cudaGetSymbolAddress((void**)&Wh,  g_Wh);
    cudaGetSymbolAddress((void**)&Wl,  g_Wl);

    cudaFuncSetAttribute(gemm_stage<false, true,  false, false>,
                         cudaFuncAttributeMaxDynamicSharedMemorySize, SMEMB);
    cudaFuncSetAttribute(gemm_stage<false, false, false, false>,
                         cudaFuncAttributeMaxDynamicSharedMemorySize, SMEMB);
    cudaFuncSetAttribute(gemm_stage<true,  true,  false, false>,
                         cudaFuncAttributeMaxDynamicSharedMemorySize, SMEMB);
    cudaFuncSetAttribute(gemm_stage<true,  true,  true,  false>,
                         cudaFuncAttributeMaxDynamicSharedMemorySize, SMEMB);
    cudaFuncSetAttribute(gemm_stage<false, false, false, true >,
                         cudaFuncAttributeMaxDynamicSharedMemorySize, SMEMB);

    // prep: hi/lo splits
    k_split_x<<<16384, 256>>>(xs, Xh, Xl);
    WPtrs wp;
    wp.p[0] = W_xh0;          wp.p[1] = W_hy0;
    wp.p[2] = W_hh_h;         wp.p[3] = W_xh_h;
    wp.p[4] = W_hy_h;         wp.p[5] = W_hh_h + WSZ;
    wp.p[6] = W_xh_h + WSZ;   wp.p[7] = W_hy_h + WSZ;
    k_split_w<<<2048, 256>>>(wp, Wh, Wl);

    dim3 grid(HD / BN, MROWS / BM);   // (2, 256)
    dim3 block(NTH);
#define WS(s) (Wh + (size_t)(s) * WSZ), (Wl + (size_t)(s) * WSZ)

    // 1) h0 = tanh(X @ W_xh0^T + b_xh0 + b_hh0)
    gemm_stage<false, true, false, false><<<grid, block, SMEMB>>>(
        Xh, Xl, WS(0), nullptr, nullptr, nullptr, nullptr,
        b_xh0, b_hh0, H0h, H0l, nullptr, nullptr);
    // 2) y0 = h0 @ W_hy0^T + b_hy0
    gemm_stage<false, false, false, false><<<grid, block, SMEMB>>>(
        H0h, H0l, WS(1), nullptr, nullptr, nullptr, nullptr,
        b_hy0, nullptr, Yh, Yl, nullptr, nullptr);
    // 3) h1 = tanh(h0 @ W_hh_h[0]^T + y0 @ W_xh_h[0]^T + biases)
    gemm_stage<true, true, false, false><<<grid, block, SMEMB>>>(
        H0h, H0l, WS(2), Yh, Yl, WS(3),
        b_hh_h, b_xh_h, H1h, H1l, nullptr, nullptr);
    // 4) y1 = h1 @ W_hy_h[0]^T + b_hy_h[0]
    gemm_stage<false, false, false, false><<<grid, block, SMEMB>>>(
        H1h, H1l, WS(4), nullptr, nullptr, nullptr, nullptr,
        b_hy_h, nullptr, Yh, Yl, nullptr, nullptr);
    // 5) h2 = tanh(h1 @ W_hh_h[1]^T + y1 @ W_xh_h[1]^T + biases) + hs_final
    gemm_stage<true, true, true, false><<<grid, block, SMEMB>>>(
        H1h, H1l, WS(5), Yh, Yl, WS(6),
        b_hh_h + HD, b_xh_h + HD, H0h, H0l, nullptr, hs_final);
    // 6) outputs = (h2 @ W_hy_h[1]^T + b_hy_h[1]) -> [S, B, H] fp32
    gemm_stage<false, false, false, true><<<grid, block, SMEMB>>>(
        H0h, H0l, WS(7), nullptr, nullptr, nullptr, nullptr,
        b_hy_h + HD, nullptr, nullptr, nullptr, out, nullptr);
#undef WS
}

// round 5
// speedup vs baseline: 3.1712x; 1.1717x over previous
#include <cuda_runtime.h>
#include <cuda_bf16.h>
#include <math.h>
#include <cstdint>
#include <cstddef>

typedef __nv_bfloat16 bf16;

#define MROWS 32768
#define HD    512
#define RSTRIDE 1024            // interleaved row stride in bf16 elems (hi+lo)
#define WELEMS  ((size_t)HD * RSTRIDE)   // one weight matrix, interleaved

#define BM 128
#define BN 128
#define KC 32
#define NTH 256

// smem: 1024 B header (bias) + 3 stages x 32 KB (A 16K + W 16K, hi/lo interleaved rows)
#define A_OFF  0u
#define W_OFF  16384u
#define STAGE  32768u
#define NSTAGE 3
#define SMEMB  (1024u + NSTAGE*STAGE)   // 99328

// ------------- scratch (static device arrays, no runtime alloc) -------------
__device__ bf16 g_Xhl [(size_t)MROWS * RSTRIDE];
__device__ bf16 g_H0hl[(size_t)MROWS * RSTRIDE];
__device__ bf16 g_H1hl[(size_t)MROWS * RSTRIDE];
__device__ bf16 g_Yhl [(size_t)MROWS * RSTRIDE];
__device__ bf16 g_Whl [8 * WELEMS];

// ----------------------------- PTX helpers ----------------------------------
__device__ __forceinline__ uint32_t s2u(const void* p) {
    uint32_t a;
    asm("{ .reg .u64 t; cvta.to.shared.u64 t, %1; cvt.u32.u64 %0, t; }" : "=r"(a) : "l"(p));
    return a;
}
__device__ __forceinline__ void cp16(uint32_t dst, const void* src) {
    asm volatile("cp.async.cg.shared.global [%0], [%1], 16;" :: "r"(dst), "l"(src));
}
#define CP_COMMIT() asm volatile("cp.async.commit_group;" ::: "memory")

__device__ __forceinline__ void ldsm4(uint32_t& r0, uint32_t& r1, uint32_t& r2,
                                      uint32_t& r3, uint32_t addr) {
    asm volatile("ldmatrix.sync.aligned.m8n8.x4.shared.b16 {%0,%1,%2,%3}, [%4];"
                 : "=r"(r0), "=r"(r1), "=r"(r2), "=r"(r3) : "r"(addr));
}
__device__ __forceinline__ void mma16816(float* c, const uint32_t* a, const uint32_t* b) {
    asm volatile(
        "mma.sync.aligned.m16n8k16.row.col.f32.bf16.bf16.f32 "
        "{%0,%1,%2,%3}, {%4,%5,%6,%7}, {%8,%9}, {%0,%1,%2,%3};"
        : "+f"(c[0]), "+f"(c[1]), "+f"(c[2]), "+f"(c[3])
        : "r"(a[0]), "r"(a[1]), "r"(a[2]), "r"(a[3]), "r"(b[0]), "r"(b[1]));
}

// fast accurate tanh: 1 - 2/(exp(2x)+1)
__device__ __forceinline__ float tfast(float x) {
    float e, r;
    asm("ex2.approx.f32 %0, %1;" : "=f"(e) : "f"(x * 2.8853900817779268f));
    asm("rcp.approx.f32 %0, %1;" : "=f"(r) : "f"(e + 1.0f));
    return fmaf(-2.0f, r, 1.0f);
}

// hi/lo split of a float into two bf16
__device__ __forceinline__ void split2(float x, bf16& h, bf16& l) {
    h = __float2bfloat16_rn(x);
    l = __float2bfloat16_rn(x - __bfloat162float(h));
}

// ---------------------------- GEMM stage kernel -----------------------------
// acc[m][n] = sum_k A0[m][k]*W0[n][k] (+A1*W1 if DUAL) + bias, opt tanh.
// All activation/weight inputs use the interleaved hi/lo row layout:
//   row = 16 chunks of [32 hi bf16 | 32 lo bf16]  (1024 elems = 2 KB per row)
// Computes Ah*Wh + Ah*Wl + Al*Wh with fp32 accumulation.
template<bool DUAL, bool DO_TANH, bool HSF, bool TRANS>
__global__ void __launch_bounds__(NTH, 2) gemm_stage(
    const bf16* __restrict__ A0, const bf16* __restrict__ W0,
    const bf16* __restrict__ A1, const bf16* __restrict__ W1,
    const float* __restrict__ bias0, const float* __restrict__ bias1,
    bf16* __restrict__ outHL, float* __restrict__ outF, float* __restrict__ hsf)
{
    extern __shared__ char smem[];
    const uint32_t sb = s2u(smem);
    const int t   = threadIdx.x;
    const int wid = t >> 5;
    const int lid = t & 31;
    const int n0  = blockIdx.x * BN;
    const int m0  = blockIdx.y * BM;
    const int wm  = wid & 3;       // 0..3 (M, 32 rows each)
    const int wn  = wid >> 2;      // 0..1 (N, 64 cols each)

    if (t < BN) {
        float b = bias0[n0 + t];
        if (bias1) b += bias1[n0 + t];
        ((float*)smem)[t] = b;
    }

    float acc[2][8][4];
#pragma unroll
    for (int mt = 0; mt < 2; ++mt)
#pragma unroll
        for (int nt = 0; nt < 8; ++nt)
#pragma unroll
            for (int e = 0; e < 4; ++e) acc[mt][nt][e] = 0.0f;

    // ldmatrix per-lane addressing (same scheme verified in R4)
    const int q   = lid >> 3;        // quadrant 0..3
    const int lr8 = lid & 7;
    const int sws = lr8;             // swizzle key = row & 7
    const uint32_t aOff = (uint32_t)((wm * 32 + (q & 1) * 8 + lr8) * 128);
    const int aHalf = q >> 1;
    const uint32_t bOff = (uint32_t)((wn * 64 + (q >> 1) * 8 + lr8) * 128);
    const int bHalf = q & 1;

    const int NC = DUAL ? 32 : 16;

    auto load_chunk = [&](int cc) {
        const bf16* A = (DUAL && cc >= 16) ? A1 : A0;
        const bf16* W = (DUAL && cc >= 16) ? W1 : W0;
        const int kc = cc & 15;
        const uint32_t st = sb + 1024 + (uint32_t)(cc % NSTAGE) * STAGE;
#pragma unroll
        for (int i = 0; i < 4; ++i) {                 // A: 128 rows x 8 chunks16
            int idx = t + i * NTH;
            int r = idx >> 3, c = idx & 7;
            uint32_t d = st + A_OFF + r * 128 + (uint32_t)((c ^ (r & 7)) << 4);
            cp16(d, A + (size_t)(m0 + r) * RSTRIDE + kc * 64 + c * 8);
        }
#pragma unroll
        for (int i = 0; i < 4; ++i) {                 // W: 128 rows x 8 chunks16
            int idx = t + i * NTH;
            int r = idx >> 3, c = idx & 7;
            uint32_t d = st + W_OFF + r * 128 + (uint32_t)((c ^ (r & 7)) << 4);
            cp16(d, W + (size_t)(n0 + r) * RSTRIDE + kc * 64 + c * 8);
        }
        CP_COMMIT();
    };

    load_chunk(0);
    load_chunk(1);

#pragma unroll 1
    for (int cc = 0; cc < NC; ++cc) {
        if (cc < NC - 1) asm volatile("cp.async.wait_group 1;" ::: "memory");
        else             asm volatile("cp.async.wait_group 0;" ::: "memory");
        __syncthreads();
        if (cc + 2 < NC) load_chunk(cc + 2);

        const uint32_t st = sb + 1024 + (uint32_t)(cc % NSTAGE) * STAGE;
        const uint32_t aB = st + A_OFF + aOff;
        const uint32_t bB = st + W_OFF + bOff;

#pragma unroll
        for (int ks = 0; ks < 2; ++ks) {
            // chunk columns: hi = 0..3, lo = 4..7 within the 128 B row
            const uint32_t caH = (uint32_t)(((2 * ks + aHalf) ^ sws) << 4);
            const uint32_t caL = (uint32_t)(((4 + 2 * ks + aHalf) ^ sws) << 4);
            const uint32_t cbH = (uint32_t)(((2 * ks + bHalf) ^ sws) << 4);
            const uint32_t cbL = (uint32_t)(((4 + 2 * ks + bHalf) ^ sws) << 4);
            uint32_t a[2][4], b[8][2];

            // A_hi
#pragma unroll
            for (int mt = 0; mt < 2; ++mt)
                ldsm4(a[mt][0], a[mt][1], a[mt][2], a[mt][3],
                      aB + mt * 2048 + caH);
            // W_lo  -> acc += Ah*Wl
#pragma unroll
            for (int bt = 0; bt < 4; ++bt)
                ldsm4(b[2*bt][0], b[2*bt][1], b[2*bt+1][0], b[2*bt+1][1],
                      bB + bt * 2048 + cbL);
#pragma unroll
            for (int mt = 0; mt < 2; ++mt)
#pragma unroll
                for (int nt = 0; nt < 8; ++nt)
                    mma16816(acc[mt][nt], a[mt], b[nt]);
            // W_hi  -> acc += Ah*Wh
#pragma unroll
            for (int bt = 0; bt < 4; ++bt)
                ldsm4(b[2*bt][0], b[2*bt][1], b[2*bt+1][0], b[2*bt+1][1],
                      bB + bt * 2048 + cbH);
#pragma unroll
            for (int mt = 0; mt < 2; ++mt)
#pragma unroll
                for (int nt = 0; nt < 8; ++nt)
                    mma16816(acc[mt][nt], a[mt], b[nt]);
            // A_lo  -> acc += Al*Wh
#pragma unroll
            for (int mt = 0; mt < 2; ++mt)
                ldsm4(a[mt][0], a[mt][1], a[mt][2], a[mt][3],
                      aB + mt * 2048 + caL);
#pragma unroll
            for (int mt = 0; mt < 2; ++mt)
#pragma unroll
                for (int nt = 0; nt < 8; ++nt)
                    mma16816(acc[mt][nt], a[mt], b[nt]);
        }
    }

    // ------------------------------ epilogue --------------------------------
    const float* bsm = (const float*)smem;
    const int lq = lid >> 2;      // row within 8
    const int lr = lid & 3;       // col pair

#pragma unroll
    for (int mt = 0; mt < 2; ++mt) {
#pragma unroll
        for (int hf = 0; hf < 2; ++hf) {
            const int m = m0 + wm * 32 + mt * 16 + lq + hf * 8;
#pragma unroll
            for (int nt = 0; nt < 8; ++nt) {
                const int n = n0 + wn * 64 + nt * 8 + lr * 2;
                float x0 = acc[mt][nt][hf * 2 + 0] + bsm[n - n0];
                float x1 = acc[mt][nt][hf * 2 + 1] + bsm[n - n0 + 1];
                if (DO_TANH) { x0 = tfast(x0); x1 = tfast(x1); }

                if (TRANS) {
                    const int s = m & 4095, bb = m >> 12;
                    float* dst = outF + ((size_t)(s * 8 + bb)) * HD + n;
                    *(float2*)dst = make_float2(x0, x1);
                } else {
                    __nv_bfloat162 hh, ll;
                    split2(x0, hh.x, ll.x);
                    split2(x1, hh.y, ll.y);
                    bf16* base = outHL + (size_t)m * RSTRIDE + (n >> 5) * 64;
                    const int w = n & 31;
                    *(__nv_bfloat162*)(base + w)      = hh;
                    *(__nv_bfloat162*)(base + 32 + w) = ll;
                }
                if (HSF && ((m & 4095) == 4095)) {
                    float* hd = hsf + (size_t)(m >> 12) * HD + n;
                    *(float2*)hd = make_float2(x0, x1);
                }
            }
        }
    }
}

// ------------------------------- prep kernels -------------------------------
// One thread handles one (row, k-chunk): reads 32 fp32, writes 32 hi + 32 lo.
__global__ void k_split_x(const float* __restrict__ x, bf16* __restrict__ dst)
{
    const size_t idx = (size_t)blockIdx.x * blockDim.x + threadIdx.x;
    const size_t row = idx >> 4;
    const int    kc  = (int)(idx & 15);
    const float* src = x + row * 512 + kc * 32;
    bf16* d = dst + row * RSTRIDE + kc * 64;

    uint32_t hi[16], lo[16];
#pragma unroll
    for (int j = 0; j < 8; ++j) {
        float4 v = *(const float4*)(src + j * 4);
        __nv_bfloat162 h0, l0, h1, l1;
        split2(v.x, h0.x, l0.x); split2(v.y, h0.y, l0.y);
        split2(v.z, h1.x, l1.x); split2(v.w, h1.y, l1.y);
        hi[2*j]   = *(uint32_t*)&h0; hi[2*j+1] = *(uint32_t*)&h1;
        lo[2*j]   = *(uint32_t*)&l0; lo[2*j+1] = *(uint32_t*)&l1;
    }
#pragma unroll
    for (int j = 0; j < 4; ++j) {
        ((uint4*)d)[j]     = *(uint4*)(hi + 4*j);
        ((uint4*)(d+32))[j]= *(uint4*)(lo + 4*j);
    }
}

struct WPtrs { const float* p[8]; };

__global__ void k_split_w(WPtrs wp, bf16* __restrict__ dst)
{
    const size_t idx = (size_t)blockIdx.x * blockDim.x + threadIdx.x;
    const int slot = (int)(idx >> 13);
    const size_t row = (idx >> 4) & 511;
    const int    kc  = (int)(idx & 15);
    const float* src = wp.p[slot] + row * 512 + kc * 32;
    bf16* d = dst + (size_t)slot * WELEMS + row * RSTRIDE + kc * 64;

    uint32_t hi[16], lo[16];
#pragma unroll
    for (int j = 0; j < 8; ++j) {
        float4 v = *(const float4*)(src + j * 4);
        __nv_bfloat162 h0, l0, h1, l1;
        split2(v.x, h0.x, l0.x); split2(v.y, h0.y, l0.y);
        split2(v.z, h1.x, l1.x); split2(v.w, h1.y, l1.y);
        hi[2*j]   = *(uint32_t*)&h0; hi[2*j+1] = *(uint32_t*)&h1;
        lo[2*j]   = *(uint32_t*)&l0; lo[2*j+1] = *(uint32_t*)&l1;
    }
#pragma unroll
    for (int j = 0; j < 4; ++j) {
        ((uint4*)d)[j]      = *(uint4*)(hi + 4*j);
        ((uint4*)(d+32))[j] = *(uint4*)(lo + 4*j);
    }
}

// --------------------------------- launcher ---------------------------------
extern "C" void kernel_launch(void* const* d_in, const int* in_sizes, int n_in,
                              void* d_out, int out_size)
{
    const float* xs     = (const float*)d_in[0];
    const float* W_xh0  = (const float*)d_in[1];
    const float* b_xh0  = (const float*)d_in[2];
    const float* b_hh0  = (const float*)d_in[4];
    const float* W_hy0  = (const float*)d_in[5];
    const float* b_hy0  = (const float*)d_in[6];
    const float* W_xh_h = (const float*)d_in[7];
    const float* b_xh_h = (const float*)d_in[8];
    const float* W_hh_h = (const float*)d_in[9];
    const float* b_hh_h = (const float*)d_in[10];
    const float* W_hy_h = (const float*)d_in[11];
    const float* b_hy_h = (const float*)d_in[12];

    float* out = (float*)d_out;
    float* hs_final = out + (size_t)4096 * 8 * HD;

    bf16 *Xhl, *H0hl, *H1hl, *Yhl, *Whl;
    cudaGetSymbolAddress((void**)&Xhl,  g_Xhl);
    cudaGetSymbolAddress((void**)&H0hl, g_H0hl);
    cudaGetSymbolAddress((void**)&H1hl, g_H1hl);
    cudaGetSymbolAddress((void**)&Yhl,  g_Yhl);
    cudaGetSymbolAddress((void**)&Whl,  g_Whl);

    cudaFuncSetAttribute(gemm_stage<false, true,  false, false>,
                         cudaFuncAttributeMaxDynamicSharedMemorySize, SMEMB);
    cudaFuncSetAttribute(gemm_stage<false, false, false, false>,
                         cudaFuncAttributeMaxDynamicSharedMemorySize, SMEMB);
    cudaFuncSetAttribute(gemm_stage<true,  true,  false, false>,
                         cudaFuncAttributeMaxDynamicSharedMemorySize, SMEMB);
    cudaFuncSetAttribute(gemm_stage<true,  true,  true,  false>,
                         cudaFuncAttributeMaxDynamicSharedMemorySize, SMEMB);
    cudaFuncSetAttribute(gemm_stage<false, false, false, true >,
                         cudaFuncAttributeMaxDynamicSharedMemorySize, SMEMB);

    // prep: hi/lo interleaved splits
    k_split_x<<<2048, 256>>>(xs, Xhl);
    WPtrs wp;
    wp.p[0] = W_xh0;          wp.p[1] = W_hy0;
    wp.p[2] = W_hh_h;         wp.p[3] = W_xh_h;
    wp.p[4] = W_hy_h;         wp.p[5] = W_hh_h + 512*512;
    wp.p[6] = W_xh_h + 512*512; wp.p[7] = W_hy_h + 512*512;
    k_split_w<<<256, 256>>>(wp, Whl);

    dim3 grid(HD / BN, MROWS / BM);   // (4, 256) = 1024 CTAs
    dim3 block(NTH);
#define WS(s) (Whl + (size_t)(s) * WELEMS)

    // 1) h0 = tanh(X @ W_xh0^T + b_xh0 + b_hh0)
    gemm_stage<false, true, false, false><<<grid, block, SMEMB>>>(
        Xhl, WS(0), nullptr, nullptr, b_xh0, b_hh0, H0hl, nullptr, nullptr);
    // 2) y0 = h0 @ W_hy0^T + b_hy0
    gemm_stage<false, false, false, false><<<grid, block, SMEMB>>>(
        H0hl, WS(1), nullptr, nullptr, b_hy0, nullptr, Yhl, nullptr, nullptr);
    // 3) h1 = tanh(h0 @ W_hh_h[0]^T + y0 @ W_xh_h[0]^T + biases)
    gemm_stage<true, true, false, false><<<grid, block, SMEMB>>>(
        H0hl, WS(2), Yhl, WS(3), b_hh_h, b_xh_h, H1hl, nullptr, nullptr);
    // 4) y1 = h1 @ W_hy_h[0]^T + b_hy_h[0]
    gemm_stage<false, false, false, false><<<grid, block, SMEMB>>>(
        H1hl, WS(4), nullptr, nullptr, b_hy_h, nullptr, Yhl, nullptr, nullptr);
    // 5) h2 = tanh(h1 @ W_hh_h[1]^T + y1 @ W_xh_h[1]^T + biases) + hs_final
    gemm_stage<true, true, true, false><<<grid, block, SMEMB>>>(
        H1hl, WS(5), Yhl, WS(6), b_hh_h + HD, b_xh_h + HD, H0hl, nullptr, hs_final);
    // 6) outputs = (h2 @ W_hy_h[1]^T + b_hy_h[1]) -> [S, B, H] fp32
    gemm_stage<false, false, false, true><<<grid, block, SMEMB>>>(
        H0hl, WS(7), nullptr, nullptr, b_hy_h + HD, nullptr, nullptr, out, nullptr);
#undef WS
}